// round 13
// baseline (speedup 1.0000x reference)
#include <cuda_runtime.h>
#include <cstddef>

// Problem dims (fixed by the reference)
#define B_   256
#define NIN  700
#define T_   100
#define H1_  2048
#define H2_  2048
#define O_   20

// ---------------------------------------------------------------------------
// Scratch (device globals; no cudaMalloc allowed)
// ---------------------------------------------------------------------------
__device__ float g_Xc [(size_t)T_ * B_ * NIN];   // x transposed to [t][b][n]
__device__ float g_Z1 [(size_t)T_ * B_ * H1_];   // x@W1^T + b1
__device__ float g_S1 [(size_t)T_ * B_ * H1_];   // layer-1 spikes
__device__ float g_C2 [(size_t)T_ * B_ * H2_];   // s1@W2^T + b2
__device__ float g_SR [(size_t)T_ * B_ * H2_];   // recurrent-layer spikes
__device__ float g_Z3 [(size_t)T_ * B_ * O_];    // s_r@W3^T + b3
__device__ float g_memr[(size_t)B_ * H2_];
__device__ float g_ahp [(size_t)B_ * H2_];

// ---------------------------------------------------------------------------
// K0: transpose data [B, NIN, T] -> Xc [T, B, NIN]
// ---------------------------------------------------------------------------
__global__ void transpose_kernel(const float* __restrict__ data)
{
    __shared__ float tile[32][33];
    int b  = blockIdx.z;
    int n0 = blockIdx.x * 32;
    int t0 = blockIdx.y * 32;
    for (int j = threadIdx.y; j < 32; j += 8) {
        int n = n0 + j, t = t0 + threadIdx.x;
        tile[j][threadIdx.x] = (n < NIN && t < T_)
            ? data[((size_t)b * NIN + n) * T_ + t] : 0.f;
    }
    __syncthreads();
    for (int j = threadIdx.y; j < 32; j += 8) {
        int t = t0 + j, n = n0 + threadIdx.x;
        if (t < T_ && n < NIN)
            g_Xc[((size_t)t * B_ + b) * NIN + n] = tile[threadIdx.x][j];
    }
}

// ---------------------------------------------------------------------------
// zero persistent recurrent state
// ---------------------------------------------------------------------------
__global__ void zero_state()
{
    int i = blockIdx.x * blockDim.x + threadIdx.x;
    if (i < B_ * H2_) { g_memr[i] = 0.f; g_ahp[i] = 0.f; }
}

// ---------------------------------------------------------------------------
// Generic TN f32 GEMM:  C[M,N] = A[M,K] * W[N,K]^T + bias
// 128x128 tile, BK=16, 256 threads, 8x8 per thread.
// M % 128 == 0, N % 128 == 0 required (true here: 25600, 2048).
// ---------------------------------------------------------------------------
__device__ __forceinline__ float4 ld4_guard(const float* p, int gk, int K)
{
    if (gk + 3 < K) return *(const float4*)p;
    float4 v = make_float4(0.f, 0.f, 0.f, 0.f);
    if (gk     < K) v.x = p[0];
    if (gk + 1 < K) v.y = p[1];
    if (gk + 2 < K) v.z = p[2];
    if (gk + 3 < K) v.w = p[3];
    return v;
}

__global__ void __launch_bounds__(256)
gemm_tn_bias(const float* __restrict__ A, int K,
             const float* __restrict__ W,
             const float* __restrict__ bias,
             float* __restrict__ C, int N)
{
    __shared__ float As[16][128];
    __shared__ float Bs[16][128];
    int bm  = blockIdx.y * 128;
    int bn  = blockIdx.x * 128;
    int tid = threadIdx.x;
    int tx  = tid & 15;          // N direction
    int ty  = tid >> 4;          // M direction

    float acc[8][8];
    #pragma unroll
    for (int m = 0; m < 8; m++)
        #pragma unroll
        for (int n = 0; n < 8; n++) acc[m][n] = 0.f;

    for (int k0 = 0; k0 < K; k0 += 16) {
        #pragma unroll
        for (int i = 0; i < 2; i++) {
            int idx = tid + i * 256;
            int row = idx >> 2;
            int kc  = (idx & 3) << 2;
            int gk  = k0 + kc;
            float4 va = ld4_guard(A + (size_t)(bm + row) * K + gk, gk, K);
            As[kc][row] = va.x; As[kc+1][row] = va.y;
            As[kc+2][row] = va.z; As[kc+3][row] = va.w;
            float4 vb = ld4_guard(W + (size_t)(bn + row) * K + gk, gk, K);
            Bs[kc][row] = vb.x; Bs[kc+1][row] = vb.y;
            Bs[kc+2][row] = vb.z; Bs[kc+3][row] = vb.w;
        }
        __syncthreads();
        #pragma unroll
        for (int kk = 0; kk < 16; kk++) {
            float ra[8], rb[8];
            *(float4*)(ra)     = *(const float4*)&As[kk][ty * 8];
            *(float4*)(ra + 4) = *(const float4*)&As[kk][ty * 8 + 4];
            *(float4*)(rb)     = *(const float4*)&Bs[kk][tx * 8];
            *(float4*)(rb + 4) = *(const float4*)&Bs[kk][tx * 8 + 4];
            #pragma unroll
            for (int m = 0; m < 8; m++)
                #pragma unroll
                for (int n = 0; n < 8; n++)
                    acc[m][n] += ra[m] * rb[n];
        }
        __syncthreads();
    }

    #pragma unroll
    for (int m = 0; m < 8; m++) {
        size_t row = (size_t)(bm + ty * 8 + m);
        #pragma unroll
        for (int n = 0; n < 8; n++) {
            int col = bn + tx * 8 + n;
            C[row * N + col] = acc[m][n] + bias[col];
        }
    }
}

// ---------------------------------------------------------------------------
// K2: layer-1 leaky recurrence over all t (elementwise, one thread per (b,h1))
// ---------------------------------------------------------------------------
__global__ void layer1_rec(const float* __restrict__ p_beta1,
                           const float* __restrict__ p_thr1)
{
    int idx = blockIdx.x * blockDim.x + threadIdx.x;   // b*H1 + h
    if (idx >= B_ * H1_) return;
    float beta = *p_beta1, thr = *p_thr1;
    float mem = 0.f;
    for (int t = 0; t < T_; t++) {
        size_t g = (size_t)t * (B_ * H1_) + idx;
        mem = beta * mem + g_Z1[g];
        float s = (mem - thr) > 0.f ? 1.f : 0.f;
        mem -= s * thr;
        g_S1[g] = s;
    }
}

// ---------------------------------------------------------------------------
// K4: one recurrent time step.
//   R = s_prev @ V^T   (64x64 tile f32 GEMM, M=256, N=2048, K=2048)
//   fused epilogue: AHP neuron update, writes s_r to SR slab.
// s_prev == nullptr at t==0 (R = 0).
// ---------------------------------------------------------------------------
__global__ void __launch_bounds__(256)
step_kernel(const float* __restrict__ s_prev,
            const float* __restrict__ V,
            const float* __restrict__ c2,     // slab t
            float* __restrict__ sr,           // slab t
            const float* __restrict__ p_beta_r, const float* __restrict__ p_thr_r,
            const float* __restrict__ p_backb,  const float* __restrict__ p_alpha)
{
    __shared__ float As[16][64];
    __shared__ float Bs[16][64];
    int bn  = blockIdx.x * 64;   // h direction (N)
    int bm  = blockIdx.y * 64;   // b direction (M)
    int tid = threadIdx.x;
    int tx  = tid & 15;
    int ty  = tid >> 4;

    float acc[4][4];
    #pragma unroll
    for (int m = 0; m < 4; m++)
        #pragma unroll
        for (int n = 0; n < 4; n++) acc[m][n] = 0.f;

    if (s_prev) {
        int row = tid >> 2;
        int kc  = (tid & 3) << 2;
        for (int k0 = 0; k0 < H2_; k0 += 16) {
            float4 va = *(const float4*)(s_prev + (size_t)(bm + row) * H2_ + k0 + kc);
            As[kc][row] = va.x; As[kc+1][row] = va.y;
            As[kc+2][row] = va.z; As[kc+3][row] = va.w;
            float4 vb = *(const float4*)(V + (size_t)(bn + row) * H2_ + k0 + kc);
            Bs[kc][row] = vb.x; Bs[kc+1][row] = vb.y;
            Bs[kc+2][row] = vb.z; Bs[kc+3][row] = vb.w;
            __syncthreads();
            #pragma unroll
            for (int kk = 0; kk < 16; kk++) {
                float ra[4], rb[4];
                *(float4*)ra = *(const float4*)&As[kk][ty * 4];
                *(float4*)rb = *(const float4*)&Bs[kk][tx * 4];
                #pragma unroll
                for (int m = 0; m < 4; m++)
                    #pragma unroll
                    for (int n = 0; n < 4; n++)
                        acc[m][n] += ra[m] * rb[n];
            }
            __syncthreads();
        }
    }

    float betar = *p_beta_r, thrr = *p_thr_r;
    float backb = *p_backb,  alph = *p_alpha;

    #pragma unroll
    for (int m = 0; m < 4; m++) {
        int b = bm + ty * 4 + m;
        #pragma unroll
        for (int n = 0; n < 4; n++) {
            int h   = bn + tx * 4 + n;
            int idx = b * H2_ + h;
            float ahpv = g_ahp[idx];
            float mem  = betar * g_memr[idx] + c2[idx] + acc[m][n] - ahpv;
            float s    = (mem - thrr) > 0.f ? 1.f : 0.f;
            mem       -= s * thrr;
            g_memr[idx] = mem;
            g_ahp[idx]  = backb * ahpv + alph * s;
            sr[idx]     = s;
        }
    }
}

// ---------------------------------------------------------------------------
// K5: Z3[row, :] = SR[row, :] @ W3^T + b3   (one block per (t,b) row)
// spikes are {0,1} -> skip zeros, pure adds (numerically exact vs fma w/ 1.0)
// ---------------------------------------------------------------------------
__global__ void __launch_bounds__(128)
gemm_w3(const float* __restrict__ W3, const float* __restrict__ b3)
{
    int row = blockIdx.x;                       // 0 .. T_*B_-1
    const float* s = g_SR + (size_t)row * H2_;
    int tid = threadIdx.x;

    float acc[O_];
    #pragma unroll
    for (int o = 0; o < O_; o++) acc[o] = 0.f;

    for (int k = tid; k < H2_; k += 128) {
        if (s[k] != 0.f) {
            #pragma unroll
            for (int o = 0; o < O_; o++) acc[o] += W3[o * H2_ + k];
        }
    }

    __shared__ float red[O_][128];
    #pragma unroll
    for (int o = 0; o < O_; o++) red[o][tid] = acc[o];
    __syncthreads();
    for (int st = 64; st > 0; st >>= 1) {
        if (tid < st) {
            #pragma unroll
            for (int o = 0; o < O_; o++) red[o][tid] += red[o][tid + st];
        }
        __syncthreads();
    }
    if (tid < O_)
        g_Z3[(size_t)row * O_ + tid] = red[tid][0] + b3[tid];
}

// ---------------------------------------------------------------------------
// K6: output leaky recurrence, writes spikes to d_out [T, B, O]
// ---------------------------------------------------------------------------
__global__ void out_rec(const float* __restrict__ p_beta2,
                        const float* __restrict__ p_thr2,
                        float* __restrict__ out)
{
    int idx = blockIdx.x * blockDim.x + threadIdx.x;   // b*O_ + o
    if (idx >= B_ * O_) return;
    float beta = *p_beta2, thr = *p_thr2;
    float mem = 0.f;
    for (int t = 0; t < T_; t++) {
        size_t g = (size_t)t * (B_ * O_) + idx;
        mem = beta * mem + g_Z3[g];
        float s = (mem - thr) > 0.f ? 1.f : 0.f;
        out[g] = s;
        mem -= s * thr;
    }
}

// ---------------------------------------------------------------------------
// Host launcher (graph-capturable: kernel launches only)
// ---------------------------------------------------------------------------
extern "C" void kernel_launch(void* const* d_in, const int* in_sizes, int n_in,
                              void* d_out, int out_size)
{
    const float* data   = (const float*)d_in[0];
    const float* W1     = (const float*)d_in[1];
    const float* b1     = (const float*)d_in[2];
    const float* W2     = (const float*)d_in[3];
    const float* b2     = (const float*)d_in[4];
    const float* V      = (const float*)d_in[5];
    const float* W3     = (const float*)d_in[6];
    const float* b3     = (const float*)d_in[7];
    const float* beta1  = (const float*)d_in[8];
    const float* thr1   = (const float*)d_in[9];
    const float* beta_r = (const float*)d_in[10];
    const float* thr_r  = (const float*)d_in[11];
    const float* backb  = (const float*)d_in[12];
    const float* alpha  = (const float*)d_in[13];
    const float* beta2  = (const float*)d_in[14];
    const float* thr2   = (const float*)d_in[15];
    float* out = (float*)d_out;

    float *pXc, *pZ1, *pS1, *pC2, *pSR;
    cudaGetSymbolAddress((void**)&pXc, g_Xc);
    cudaGetSymbolAddress((void**)&pZ1, g_Z1);
    cudaGetSymbolAddress((void**)&pS1, g_S1);
    cudaGetSymbolAddress((void**)&pC2, g_C2);
    cudaGetSymbolAddress((void**)&pSR, g_SR);

    // K0: transpose input to [t][b][n]
    transpose_kernel<<<dim3((NIN + 31) / 32, (T_ + 31) / 32, B_), dim3(32, 8)>>>(data);

    // zero recurrent state
    zero_state<<<(B_ * H2_ + 255) / 256, 256>>>();

    // K1: Z1 = Xc @ W1^T + b1   ([25600, 700] x [700, 2048])
    gemm_tn_bias<<<dim3(H1_ / 128, (T_ * B_) / 128), 256>>>(pXc, NIN, W1, b1, pZ1, H1_);

    // K2: layer-1 leaky recurrence -> S1
    layer1_rec<<<(B_ * H1_ + 255) / 256, 256>>>(beta1, thr1);

    // K3: C2 = S1 @ W2^T + b2   ([25600, 2048] x [2048, 2048])
    gemm_tn_bias<<<dim3(H2_ / 128, (T_ * B_) / 128), 256>>>(pS1, H1_, W2, b2, pC2, H2_);

    // K4: sequential recurrent AHP steps (V GEMM fused with neuron update)
    for (int t = 0; t < T_; t++) {
        const float* sp = (t == 0) ? nullptr : (pSR + (size_t)(t - 1) * B_ * H2_);
        step_kernel<<<dim3(H2_ / 64, B_ / 64), 256>>>(
            sp, V,
            pC2 + (size_t)t * B_ * H2_,
            pSR + (size_t)t * B_ * H2_,
            beta_r, thr_r, backb, alpha);
    }

    // K5: Z3 = SR @ W3^T + b3
    gemm_w3<<<T_ * B_, 128>>>(W3, b3);

    // K6: output leaky recurrence -> spikes
    out_rec<<<(B_ * O_ + 255) / 256, 256>>>(beta2, thr2, out);
}